// round 3
// baseline (speedup 1.0000x reference)
#include <cuda_runtime.h>

// ComNet: R=64 runs, T=256 timesteps, N=1024 agents, MLP 4->10(tanh)->2.
// Wavefront over B=4 agent blocks: thread t computes block b = s - 2t at step s.
// Per-warp asynchronous loops: cross-warp handoff (warp w-1 lane31 -> warp w
// lane0) via smem ring + release/acquire stamp; producer leads by 64 steps.

#define R_ 64
#define T_ 256
#define N_ 1024
#define NB_ 256                   // blocks per row (N/4)
#define ITERS_ 319                // per-warp steps: 62 intra-warp skew + 256 + tail
#define RINGD_ 512                // > ITERS_, power of 2 -> no slot reuse

__device__ __forceinline__ float fast_rcp(float x) {
    float r; asm("rcp.approx.f32 %0, %1;" : "=f"(r) : "f"(x)); return r;
}
__device__ __forceinline__ float fast_ex2(float x) {
    float r; asm("ex2.approx.f32 %0, %1;" : "=f"(r) : "f"(x)); return r;
}

__global__ __launch_bounds__(256, 1)
void comnet_kernel(const float* __restrict__ runs,
                   const float* __restrict__ comm0,
                   const float* __restrict__ w1,
                   const float* __restrict__ b1,
                   const float* __restrict__ w2,
                   const float* __restrict__ b2,
                   float* __restrict__ out)
{
    extern __shared__ unsigned char dynsm[];
    float4* ring  = (float4*)dynsm;                               // [7][RINGD_]
    int*    stamp = (int*)(dynsm + 7 * RINGD_ * sizeof(float4));  // [7]

    const int r    = blockIdx.x;
    const int t    = threadIdx.x;
    const int lane = t & 31;
    const int warp = t >> 5;
    const int wbase = 64 * warp;

    if (t < 7) stamp[t] = 0;
    __syncthreads();   // only barrier in the kernel

    const unsigned stamp_me   = (unsigned)__cvta_generic_to_shared(&stamp[warp]);
    const unsigned stamp_prev = (warp > 0)
        ? (unsigned)__cvta_generic_to_shared(&stamp[warp - 1]) : 0u;
    float4* ring_me   = ring + (size_t)warp * RINGD_;        // producer slots
    float4* ring_prev = (warp > 0) ? ring + (size_t)(warp - 1) * RINGD_ : ring;

    // ---- weights in registers ----
    float W1[40], B1[10], W2[20];
#pragma unroll
    for (int k = 0; k < 40; ++k) W1[k] = w1[k];
#pragma unroll
    for (int k = 0; k < 10; ++k) B1[k] = b1[k];
#pragma unroll
    for (int k = 0; k < 20; ++k) W2[k] = w2[k];
    const float B2lo = b2[0];
    const float B2hi = b2[1];

    const float4* __restrict__ xrow4 =
        (const float4*)(runs + ((size_t)r * T_ + t) * (size_t)N_ * 2);
    float4* __restrict__ orow4 = (float4*)(out + ((size_t)r * T_ + t) * N_);
    const float* __restrict__ c0row = comm0 + (size_t)r * N_;

    float4 h1 = make_float4(0.f, 0.f, 0.f, 0.f);   // own block @ s-1
    float4 h2 = h1;                                // own block @ s-2

    // prefetch: lane 0 of every warp is active at it=0 (its block 0)
    float4 px0 = h1, px1 = h1, pc0 = h1;
    if (lane == 0) { px0 = xrow4[0]; px1 = xrow4[1]; }
    if (t == 0)    pc0 = make_float4(c0row[1], c0row[2], c0row[3], c0row[4]);

    for (int it = 0; it < ITERS_; ++it) {
        const int s = wbase + it;
        const int b = s - 2 * t;
        const bool active = ((unsigned)b < (unsigned)NB_);

        // ---- right values c(t-1, 4b+1..4b+4): intra-warp via shuffles ----
        float r0 = __shfl_up_sync(0xffffffffu, h2.y, 1);
        float r1 = __shfl_up_sync(0xffffffffu, h2.z, 1);
        float r2 = __shfl_up_sync(0xffffffffu, h2.w, 1);
        float r3 = __shfl_up_sync(0xffffffffu, h1.x, 1);

        // cross-warp handoff for lane 0 (needed only while lane 0 active)
        if (warp > 0 && it < NB_) {
            if (lane == 0) {
                int st;
                do {
                    asm volatile("ld.acquire.cta.shared.b32 %0, [%1];"
                                 : "=r"(st) : "r"(stamp_prev) : "memory");
                } while (st < s);
                float4 pkg = ring_prev[s & (RINGD_ - 1)];
                r0 = pkg.x; r1 = pkg.y; r2 = pkg.z; r3 = pkg.w;
            }
        }
        if (t == 0) { r0 = pc0.x; r1 = pc0.y; r2 = pc0.z; r3 = pc0.w; }
        if (b == NB_ - 1) r3 = 0.0f;      // zero right boundary for agent N-1

        const float4 cx0 = px0, cx1 = px1;

        // ---- prefetch next block's inputs ----
        const int bn = s + 1 - 2 * t;
        if ((unsigned)bn < (unsigned)NB_) {
            px0 = xrow4[2 * bn];
            px1 = xrow4[2 * bn + 1];
            if (t == 0) {
                const int base = 4 * bn;
                pc0 = make_float4(c0row[base + 1], c0row[base + 2],
                                  c0row[base + 3],
                                  (bn < NB_ - 1) ? c0row[base + 4] : 0.0f);
            }
        }

        float4 cur = h1;
        if (active) {
            float o0v[4], o1v[4];
            float lf = (b == 0) ? 0.0f : h1.w;          // c(t, 4b-1)
#pragma unroll
            for (int k = 0; k < 4; ++k) {
                const float xx = (k == 0) ? cx0.x : (k == 1) ? cx0.z
                                : (k == 2) ? cx1.x : cx1.z;
                const float xy = (k == 0) ? cx0.y : (k == 1) ? cx0.w
                                : (k == 2) ? cx1.y : cx1.w;
                const float rt = (k == 0) ? r0 : (k == 1) ? r1
                                : (k == 2) ? r2 : r3;

                float a0 = B2lo, a0b = 0.f, a1 = B2hi, a1b = 0.f;
#pragma unroll
                for (int j = 0; j < 10; j += 2) {
                    // two hidden units; lf folded in LAST (shortest chain)
                    float aj = fmaf(W1[4 * j + 0], xx, B1[j]);
                    aj       = fmaf(W1[4 * j + 1], xy, aj);
                    aj       = fmaf(W1[4 * j + 3], rt, aj);
                    aj       = fmaf(W1[4 * j + 2], lf, aj);
                    float ak = fmaf(W1[4 * j + 4], xx, B1[j + 1]);
                    ak       = fmaf(W1[4 * j + 5], xy, ak);
                    ak       = fmaf(W1[4 * j + 7], rt, ak);
                    ak       = fmaf(W1[4 * j + 6], lf, ak);
                    aj = fminf(aj, 15.0f);      // overflow clamp (ALU pipe)
                    ak = fminf(ak, 15.0f);
                    // tanh(x) = 1 - 2/(1+e^{2x}); one rcp serves both units
                    const float e0 = fast_ex2(aj * 2.8853900817779268f);
                    const float e1 = fast_ex2(ak * 2.8853900817779268f);
                    const float d0 = e0 + 1.0f;
                    const float d1 = e1 + 1.0f;
                    const float rr = fast_rcp(d0 * d1);
                    const float hj = fmaf(-2.0f, rr * d1, 1.0f);
                    const float hk = fmaf(-2.0f, rr * d0, 1.0f);
                    a0  = fmaf(W2[j],          hj, a0);
                    a0b = fmaf(W2[j + 1],      hk, a0b);
                    a1  = fmaf(W2[10 + j],     hj, a1);
                    a1b = fmaf(W2[10 + j + 1], hk, a1b);
                }
                o0v[k] = a0 + a0b;
                const float o1 = a1 + a1b;
                o1v[k] = o1;
                lf = o1;                          // left-chain within block
            }
            orow4[b] = make_float4(o0v[0], o0v[1], o0v[2], o0v[3]);
            cur = make_float4(o1v[0], o1v[1], o1v[2], o1v[3]);
        }

        // ---- publish package for consumer step s+1 (pre-shift h1 + cur) ----
        if (warp < 7 && lane == 31) {
            ring_me[(s + 1) & (RINGD_ - 1)] = make_float4(h1.y, h1.z, h1.w, cur.x);
            asm volatile("st.release.cta.shared.b32 [%0], %1;"
                         :: "r"(stamp_me), "r"(s + 1) : "memory");
        }

        h2 = h1;
        if (active) h1 = cur;
    }
}

extern "C" void kernel_launch(void* const* d_in, const int* in_sizes, int n_in,
                              void* d_out, int out_size)
{
    const float* runs  = (const float*)d_in[0];
    const float* comm0 = (const float*)d_in[1];
    const float* w1    = (const float*)d_in[2];
    const float* b1    = (const float*)d_in[3];
    const float* w2    = (const float*)d_in[4];
    const float* b2    = (const float*)d_in[5];
    float* out = (float*)d_out;

    const int smem = 7 * RINGD_ * sizeof(float4) + 7 * sizeof(int);
    cudaFuncSetAttribute(comnet_kernel,
                         cudaFuncAttributeMaxDynamicSharedMemorySize, smem);
    comnet_kernel<<<R_, T_, smem>>>(runs, comm0, w1, b1, w2, b2, out);
}

// round 4
// speedup vs baseline: 1.9131x; 1.9131x over previous
#include <cuda_runtime.h>

// ComNet: R=64 runs, T=256 timesteps, N=1024 agents, MLP 4->10(tanh)->2.
// Wavefront over B=4 agent blocks; thread with global timestep t computes
// block b = s - 2t at wavefront step s. Each run is split across a 2-CTA
// cluster along T: rank0 owns t in [0,128), rank1 owns t in [128,256).
// Intra-CTA handoff: shuffles + 3-deep smem ring + __syncthreads per step.
// Cross-CTA handoff (t=127 -> t=128): deep package ring in rank0 smem,
// release/acquire stamp over DSMEM.

#define R_   64
#define T_   256
#define N_   1024
#define NB_  256          // agent blocks per row (N/4)
#define XRD_ 512          // cross-CTA ring depth (stamps <= 511 -> no reuse)

__device__ __forceinline__ float fast_rcp(float x) {
    float r; asm("rcp.approx.f32 %0, %1;" : "=f"(r) : "f"(x)); return r;
}
__device__ __forceinline__ float fast_ex2(float x) {
    float r; asm("ex2.approx.f32 %0, %1;" : "=f"(r) : "f"(x)); return r;
}

__global__ __launch_bounds__(128, 1) __cluster_dims__(2, 1, 1)
void comnet_kernel(const float* __restrict__ runs,
                   const float* __restrict__ comm0,
                   const float* __restrict__ w1,
                   const float* __restrict__ b1,
                   const float* __restrict__ w2,
                   const float* __restrict__ b2,
                   float* __restrict__ out)
{
    __shared__ float4 ring[3][4];       // intra-CTA warp handoff
    __shared__ float4 xring[XRD_];      // cross-CTA packages (rank0's used)
    __shared__ int    xstamp;

    const int rank = blockIdx.x & 1;            // cluster cta rank
    const int r    = blockIdx.x >> 1;           // run
    const int lt   = threadIdx.x;               // 0..127
    const int t    = (rank << 7) + lt;          // global timestep
    const int lane = lt & 31;
    const int lw   = lt >> 5;                   // local warp 0..3

    if (lt == 0) xstamp = 0;
    __syncthreads();
    asm volatile("barrier.cluster.arrive.aligned;" ::: "memory");
    asm volatile("barrier.cluster.wait.aligned;" ::: "memory");

    // remote (rank0) addresses for rank1's consumer lane
    unsigned xstamp_rem = 0, xring_rem = 0;
    {
        unsigned sl = (unsigned)__cvta_generic_to_shared(&xstamp);
        unsigned rl = (unsigned)__cvta_generic_to_shared(xring);
        asm("mapa.shared::cluster.u32 %0, %1, %2;" : "=r"(xstamp_rem) : "r"(sl), "r"(0));
        asm("mapa.shared::cluster.u32 %0, %1, %2;" : "=r"(xring_rem)  : "r"(rl), "r"(0));
    }
    unsigned xstamp_loc = (unsigned)__cvta_generic_to_shared(&xstamp);

    // ---- weights in registers; fold 2/ln2 tanh scale into W1/B1 ----
    const float SC = 2.8853900817779268f;   // 2/ln(2)
    float W1[40], B1[10], W2[20];
#pragma unroll
    for (int k = 0; k < 40; ++k) W1[k] = w1[k] * SC;
#pragma unroll
    for (int k = 0; k < 10; ++k) B1[k] = b1[k] * SC;
#pragma unroll
    for (int k = 0; k < 20; ++k) W2[k] = w2[k];
    const float B2lo = b2[0];
    const float B2hi = b2[1];

    const float4* __restrict__ xrow4 =
        (const float4*)(runs + ((size_t)r * T_ + t) * (size_t)N_ * 2);
    float4* __restrict__ orow4 = (float4*)(out + ((size_t)r * T_ + t) * N_);
    const float* __restrict__ c0row = comm0 + (size_t)r * N_;

    float4 h1 = make_float4(0.f, 0.f, 0.f, 0.f);   // own block @ s-1
    float4 h2 = h1;                                // own block @ s-2

    const int sbeg = rank ? 256 : 0;
    const int send = rank ? 766 : 511;   // rank0 runs one extra publish step

    // prefetch inputs for first step
    float4 px0 = h1, px1 = h1, pc0 = h1;
    {
        const int b0 = sbeg - 2 * t;
        if ((unsigned)b0 < (unsigned)NB_) { px0 = xrow4[2 * b0]; px1 = xrow4[2 * b0 + 1]; }
        if (t == 0) pc0 = make_float4(c0row[1], c0row[2], c0row[3], c0row[4]);
    }

    for (int s = sbeg; s < send; ++s) {
        const int b = s - 2 * t;
        const bool active = ((unsigned)b < (unsigned)NB_);

        // ---- right values c(t-1, 4b+1..4b+4): intra-warp via shuffles ----
        float r0 = __shfl_up_sync(0xffffffffu, h2.y, 1);
        float r1 = __shfl_up_sync(0xffffffffu, h2.z, 1);
        float r2 = __shfl_up_sync(0xffffffffu, h2.w, 1);
        float r3 = __shfl_up_sync(0xffffffffu, h1.x, 1);

        if (lane == 0) {
            if (lw > 0) {
                float4 g2 = ring[(s + 1) % 3][lw - 1];   // producer block @ s-2
                float4 g1 = ring[(s + 2) % 3][lw - 1];   // producer block @ s-1
                r0 = g2.y; r1 = g2.z; r2 = g2.w; r3 = g1.x;
            } else if (rank == 1 && (s - 256) < NB_) {
                // cross-CTA: wait for rank0's package for step s
                int st;
                do {
                    asm volatile("ld.acquire.cluster.shared::cluster.b32 %0, [%1];"
                                 : "=r"(st) : "r"(xstamp_rem) : "memory");
                } while (st < s);
                float4 pkg;
                asm volatile("ld.shared::cluster.v4.f32 {%0,%1,%2,%3}, [%4];"
                             : "=f"(pkg.x), "=f"(pkg.y), "=f"(pkg.z), "=f"(pkg.w)
                             : "r"(xring_rem + (unsigned)((s & (XRD_ - 1)) * 16))
                             : "memory");
                r0 = pkg.x; r1 = pkg.y; r2 = pkg.z; r3 = pkg.w;
            }
        }
        if (t == 0) { r0 = pc0.x; r1 = pc0.y; r2 = pc0.z; r3 = pc0.w; }
        if (b == NB_ - 1) r3 = 0.0f;     // zero right boundary for agent N-1

        const float4 cx0 = px0, cx1 = px1;

        // ---- prefetch next step's block inputs ----
        const int bn = s + 1 - 2 * t;
        if ((unsigned)bn < (unsigned)NB_) {
            px0 = xrow4[2 * bn];
            px1 = xrow4[2 * bn + 1];
            if (t == 0) {
                const int base = 4 * bn;
                pc0 = make_float4(c0row[base + 1], c0row[base + 2],
                                  c0row[base + 3],
                                  (bn < NB_ - 1) ? c0row[base + 4] : 0.0f);
            }
        }

        float4 cur = h1;
        if (active) {
            float o0v[4], o1v[4];
            float lf = (b == 0) ? 0.0f : h1.w;           // c(t, 4b-1)
#pragma unroll
            for (int k = 0; k < 4; ++k) {
                const float xx = (k == 0) ? cx0.x : (k == 1) ? cx0.z
                                : (k == 2) ? cx1.x : cx1.z;
                const float xy = (k == 0) ? cx0.y : (k == 1) ? cx0.w
                                : (k == 2) ? cx1.y : cx1.w;
                const float rt = (k == 0) ? r0 : (k == 1) ? r1
                                : (k == 2) ? r2 : r3;

                float a0 = B2lo, a0b = 0.f, a1 = B2hi, a1b = 0.f;
#pragma unroll
                for (int j = 0; j < 10; j += 2) {
                    float aj = fmaf(W1[4 * j + 0], xx, B1[j]);
                    aj       = fmaf(W1[4 * j + 1], xy, aj);
                    aj       = fmaf(W1[4 * j + 3], rt, aj);
                    aj       = fmaf(W1[4 * j + 2], lf, aj);    // lf last: shortest chain
                    float ak = fmaf(W1[4 * j + 4], xx, B1[j + 1]);
                    ak       = fmaf(W1[4 * j + 5], xy, ak);
                    ak       = fmaf(W1[4 * j + 7], rt, ak);
                    ak       = fmaf(W1[4 * j + 6], lf, ak);
                    aj = fminf(aj, 44.0f);     // keep paired product finite
                    ak = fminf(ak, 44.0f);
                    // tanh(x) = 1 - 2/(1+2^(2x/ln2)); one rcp serves two units
                    const float e0 = fast_ex2(aj);
                    const float e1 = fast_ex2(ak);
                    const float d0 = e0 + 1.0f;
                    const float d1 = e1 + 1.0f;
                    const float rr = fast_rcp(d0 * d1);
                    const float hj = fmaf(-2.0f, rr * d1, 1.0f);
                    const float hk = fmaf(-2.0f, rr * d0, 1.0f);
                    a0  = fmaf(W2[j],          hj, a0);
                    a0b = fmaf(W2[j + 1],      hk, a0b);
                    a1  = fmaf(W2[10 + j],     hj, a1);
                    a1b = fmaf(W2[10 + j + 1], hk, a1b);
                }
                o0v[k] = a0 + a0b;
                const float o1 = a1 + a1b;
                o1v[k] = o1;
                lf = o1;                         // left-chain within block
            }
            orow4[b] = make_float4(o0v[0], o0v[1], o0v[2], o0v[3]);
            cur = make_float4(o1v[0], o1v[1], o1v[2], o1v[3]);
        }

        // ---- publish handoff packages ----
        if (lane == 31) {
            if (lw < 3) {
                ring[s % 3][lw] = cur;           // intra-CTA
            } else if (rank == 0) {
                // cross-CTA package for consumer step s+1:
                // producer block @ s-1 (.y,.z,.w) + block @ s (.x)
                xring[(s + 1) & (XRD_ - 1)] = make_float4(h1.y, h1.z, h1.w, cur.x);
                asm volatile("st.release.cluster.shared.b32 [%0], %1;"
                             :: "r"(xstamp_loc), "r"(s + 1) : "memory");
            }
        }

        h2 = h1;
        if (active) h1 = cur;
        __syncthreads();
    }

    // keep rank0's smem alive until rank1 has consumed all packages
    asm volatile("barrier.cluster.arrive.aligned;" ::: "memory");
    asm volatile("barrier.cluster.wait.aligned;" ::: "memory");
}

extern "C" void kernel_launch(void* const* d_in, const int* in_sizes, int n_in,
                              void* d_out, int out_size)
{
    const float* runs  = (const float*)d_in[0];
    const float* comm0 = (const float*)d_in[1];
    const float* w1    = (const float*)d_in[2];
    const float* b1    = (const float*)d_in[3];
    const float* w2    = (const float*)d_in[4];
    const float* b2    = (const float*)d_in[5];
    float* out = (float*)d_out;

    comnet_kernel<<<2 * R_, 128>>>(runs, comm0, w1, b1, w2, b2, out);
}

// round 5
// speedup vs baseline: 2.7242x; 1.4239x over previous
#include <cuda_runtime.h>

// ComNet: R=64 runs, T=256 timesteps, N=1024 agents, MLP 4->10(tanh)->2.
// Wavefront over B=4 agent blocks: thread t (one per timestep) computes block
// b = s - 2t at step s. One CTA per run, 256 threads. Intra-warp handoff via
// shuffles; warp boundary via 3-deep smem ring + one __syncthreads per step.
// Activation uses HW tanh.approx.f32 (1 MUFU op).

#define R_ 64
#define T_ 256
#define N_ 1024
#define NB_ 256                       // blocks per row (N/4)
#define NSTEP_ (2 * (T_ - 1) + NB_)   // 766 wavefront steps

__device__ __forceinline__ float htanh(float x) {
    float r; asm("tanh.approx.f32 %0, %1;" : "=f"(r) : "f"(x)); return r;
}

__global__ __launch_bounds__(256, 1)
void comnet_kernel(const float* __restrict__ runs,
                   const float* __restrict__ comm0,
                   const float* __restrict__ w1,
                   const float* __restrict__ b1,
                   const float* __restrict__ w2,
                   const float* __restrict__ b2,
                   float* __restrict__ out)
{
    const int r    = blockIdx.x;
    const int t    = threadIdx.x;
    const int lane = t & 31;
    const int warp = t >> 5;

    // 3-deep ring for warp-boundary block exchange (lane31 -> next warp lane0)
    __shared__ float4 ring[3][8];

    // ---- weights in registers ----
    float W1[40], B1[10], W2[20];
#pragma unroll
    for (int k = 0; k < 40; ++k) W1[k] = w1[k];
#pragma unroll
    for (int k = 0; k < 10; ++k) B1[k] = b1[k];
#pragma unroll
    for (int k = 0; k < 20; ++k) W2[k] = w2[k];
    const float B2lo = b2[0];
    const float B2hi = b2[1];

    const float4* __restrict__ xrow4 =
        (const float4*)(runs + ((size_t)r * T_ + t) * (size_t)N_ * 2);
    float4* __restrict__ orow4 = (float4*)(out + ((size_t)r * T_ + t) * N_);
    const float* __restrict__ c0row = comm0 + (size_t)r * N_;

    float4 h1 = make_float4(0.f, 0.f, 0.f, 0.f);   // own block @ s-1
    float4 h2 = h1;                                // own block @ s-2

    // prefetch buffers (first active block is b=0 at s=2t)
    float4 px0 = h1, px1 = h1, pc0 = h1;
    if (t == 0) {
        px0 = xrow4[0];
        px1 = xrow4[1];
        pc0 = make_float4(c0row[1], c0row[2], c0row[3], c0row[4]);
    }

    // rotating ring phase: p2 = (s-2)%3, p1 = (s-1)%3, p0 = s%3
    int p0 = 0, p1 = 2, p2 = 1;

    for (int s = 0; s < NSTEP_; ++s) {
        const int b = s - 2 * t;
        const bool active = ((unsigned)b < (unsigned)NB_);

        // ---- right values c(t-1, 4b+1..4b+4) ----
        float r0 = __shfl_up_sync(0xffffffffu, h2.y, 1);
        float r1 = __shfl_up_sync(0xffffffffu, h2.z, 1);
        float r2 = __shfl_up_sync(0xffffffffu, h2.w, 1);
        float r3 = __shfl_up_sync(0xffffffffu, h1.x, 1);
        if (lane == 0) {
            const int pw = (warp > 0) ? (warp - 1) : 0;
            float4 g2 = ring[p2][pw];   // producer block @ s-2
            float4 g1 = ring[p1][pw];   // producer block @ s-1
            r0 = g2.y; r1 = g2.z; r2 = g2.w; r3 = g1.x;
        }
        if (t == 0) { r0 = pc0.x; r1 = pc0.y; r2 = pc0.z; r3 = pc0.w; }
        if (b == NB_ - 1) r3 = 0.0f;    // zero right boundary for agent N-1

        const float4 cx0 = px0, cx1 = px1;

        // ---- prefetch next step's block inputs ----
        const int bn = s + 1 - 2 * t;
        if ((unsigned)bn < (unsigned)NB_) {
            px0 = xrow4[2 * bn];
            px1 = xrow4[2 * bn + 1];
            if (t == 0) {
                const int base = 4 * bn;
                pc0 = make_float4(c0row[base + 1], c0row[base + 2],
                                  c0row[base + 3],
                                  (bn < NB_ - 1) ? c0row[base + 4] : 0.0f);
            }
        }

        float4 cur = h1;
        if (active) {
            float o0v[4], o1v[4];
            float lf = (b == 0) ? 0.0f : h1.w;     // c(t, 4b-1)
#pragma unroll
            for (int k = 0; k < 4; ++k) {
                const float xx = (k == 0) ? cx0.x : (k == 1) ? cx0.z
                                : (k == 2) ? cx1.x : cx1.z;
                const float xy = (k == 0) ? cx0.y : (k == 1) ? cx0.w
                                : (k == 2) ? cx1.y : cx1.w;
                const float rt = (k == 0) ? r0 : (k == 1) ? r1
                                : (k == 2) ? r2 : r3;

                float a0 = B2lo, a0b = 0.f, a1 = B2hi, a1b = 0.f;
#pragma unroll
                for (int j = 0; j < 10; ++j) {
                    float a = fmaf(W1[4 * j + 0], xx, B1[j]);
                    a       = fmaf(W1[4 * j + 1], xy, a);
                    a       = fmaf(W1[4 * j + 3], rt, a);
                    a       = fmaf(W1[4 * j + 2], lf, a);   // lf last: shortest chain
                    const float h = htanh(a);               // HW MUFU.TANH
                    if (j & 1) { a0b = fmaf(W2[j], h, a0b); a1b = fmaf(W2[10 + j], h, a1b); }
                    else       { a0  = fmaf(W2[j], h, a0);  a1  = fmaf(W2[10 + j], h, a1); }
                }
                o0v[k] = a0 + a0b;
                const float o1 = a1 + a1b;
                o1v[k] = o1;
                lf = o1;                           // left-chain within block
            }
            orow4[b] = make_float4(o0v[0], o0v[1], o0v[2], o0v[3]);
            cur = make_float4(o1v[0], o1v[1], o1v[2], o1v[3]);
        }

        // publish warp-boundary block; shift history
        if (lane == 31 && active) ring[p0][warp] = cur;
        h2 = h1;
        if (active) h1 = cur;

        // rotate ring phases: next step's (p2,p1,p0) = (p1,p0,p0+1 mod 3)
        const int pn = p2;   // reuse oldest slot
        p2 = p1; p1 = p0; p0 = pn;

        __syncthreads();
    }
}

extern "C" void kernel_launch(void* const* d_in, const int* in_sizes, int n_in,
                              void* d_out, int out_size)
{
    const float* runs  = (const float*)d_in[0];
    const float* comm0 = (const float*)d_in[1];
    const float* w1    = (const float*)d_in[2];
    const float* b1    = (const float*)d_in[3];
    const float* w2    = (const float*)d_in[4];
    const float* b2    = (const float*)d_in[5];
    float* out = (float*)d_out;

    comnet_kernel<<<R_, T_>>>(runs, comm0, w1, b1, w2, b2, out);
}